// round 7
// baseline (speedup 1.0000x reference)
#include <cuda_runtime.h>
#include <cstdint>
#include <cstddef>

#define NB 32
#define NT 2048
#define ND 512
#define NROWS (NB*NT)   // 65536

// ---------------- scratch (static device arrays; no allocation) ----------------
__device__ float g_xn [(size_t)NROWS*ND];
__device__ float g_nh [(size_t)NROWS*ND];
__device__ float g_ifb[(size_t)NROWS*ND];
__device__ float g_hf [(size_t)NROWS*ND];
__device__ float g_h0 [(size_t)NROWS*ND];
__device__ float g_h1 [(size_t)NROWS*ND];

// ---------------- rmsnorm ----------------
__global__ __launch_bounds__(256) void rmsnorm_kernel(
    const float* __restrict__ x, const float* __restrict__ gamma,
    float* __restrict__ xn)
{
    int row = blockIdx.x * 8 + (threadIdx.x >> 5);
    int l = threadIdx.x & 31;
    const float4* xr = (const float4*)(x + (size_t)row * ND);
    const float4* gp = (const float4*)gamma;
    float4 v[4];
    float ss = 0.f;
#pragma unroll
    for (int i = 0; i < 4; i++) {
        v[i] = xr[l + 32*i];
        ss += v[i].x*v[i].x + v[i].y*v[i].y + v[i].z*v[i].z + v[i].w*v[i].w;
    }
#pragma unroll
    for (int o = 16; o > 0; o >>= 1) ss += __shfl_xor_sync(0xffffffffu, ss, o);
    float n = fmaxf(sqrtf(ss), 1e-12f);
    float s = 22.627416997969522f / n;
    float4* orow = (float4*)(xn + (size_t)row * ND);
#pragma unroll
    for (int i = 0; i < 4; i++) {
        float4 g4 = gp[l + 32*i];
        float4 o;
        o.x = v[i].x * s * (g4.x + 1.f);
        o.y = v[i].y * s * (g4.y + 1.f);
        o.z = v[i].z * s * (g4.z + 1.f);
        o.w = v[i].w * s * (g4.w + 1.f);
        orow[l + 32*i] = o;
    }
}

// ---------------- fp32 SGEMM (proven ~0.85ms): C = A @ W, opt tanh ----------------
template<int ACT>
__global__ __launch_bounds__(256) void sgemm_kernel(
    const float* __restrict__ A, const float* __restrict__ W,
    float* __restrict__ C)
{
    __shared__ float As[8][128];
    __shared__ float Bs[8][128];
    const int tid  = threadIdx.x;
    const int aRow = tid >> 1;
    const int aCol = (tid & 1) * 4;
    const int bRow = tid >> 5;
    const int bCol = (tid & 31) * 4;
    const int tr = tid >> 4;   // 0..15
    const int tc = tid & 15;   // 0..15
    const float* Ap = A + ((size_t)blockIdx.x * 128 + aRow) * ND + aCol;
    const float* Wp = W + (size_t)bRow * ND + blockIdx.y * 128 + bCol;
    float acc[8][8];
#pragma unroll
    for (int i = 0; i < 8; i++)
#pragma unroll
        for (int j = 0; j < 8; j++) acc[i][j] = 0.f;

    for (int k0 = 0; k0 < ND; k0 += 8) {
        float4 a4 = *(const float4*)(Ap + k0);
        float4 b4 = *(const float4*)(Wp + (size_t)k0 * ND);
        As[aCol+0][aRow] = a4.x;
        As[aCol+1][aRow] = a4.y;
        As[aCol+2][aRow] = a4.z;
        As[aCol+3][aRow] = a4.w;
        *(float4*)&Bs[bRow][bCol] = b4;
        __syncthreads();
#pragma unroll
        for (int kk = 0; kk < 8; kk++) {
            float ra[8], rb[8];
#pragma unroll
            for (int i = 0; i < 8; i++) ra[i] = As[kk][tr*8 + i];
#pragma unroll
            for (int j = 0; j < 8; j++) rb[j] = Bs[kk][tc*8 + j];
#pragma unroll
            for (int i = 0; i < 8; i++)
#pragma unroll
                for (int j = 0; j < 8; j++)
                    acc[i][j] = fmaf(ra[i], rb[j], acc[i][j]);
        }
        __syncthreads();
    }

    float* Cp = C + ((size_t)blockIdx.x * 128 + tr*8) * ND + blockIdx.y * 128 + tc*8;
#pragma unroll
    for (int i = 0; i < 8; i++) {
        float vv[8];
#pragma unroll
        for (int j = 0; j < 8; j++) {
            float v = acc[i][j];
            if (ACT == 1) v = tanhf(v);
            vv[j] = v;
        }
        *(float4*)(Cp + (size_t)i * ND)     = make_float4(vv[0], vv[1], vv[2], vv[3]);
        *(float4*)(Cp + (size_t)i * ND + 4) = make_float4(vv[4], vv[5], vv[6], vv[7]);
    }
}

// ---------------- sequential LRU scan, v3 ----------------
// 16 clusters x 8 CTAs = 128 SMs. Each cluster: 2 batches (cid, cid+16).
// CTA owns 64 columns; 8 threads/column (sub = tid&7, k-range 64). W is FULLY
// register-resident (32 b64/thread) -> zero W smem traffic. h chunks read from
// smem with 4-way lane broadcast (128B distinct/LDS, conflict-free). One
// cluster barrier per step covers both batches.
__global__ __launch_bounds__(512, 1) void scan_kernel(
    const float* __restrict__ nh, const float* __restrict__ ifg,
    const float* __restrict__ Whf, const float* __restrict__ bhf,
    float* __restrict__ hout)
{
    __shared__ float hbuf[2][2][512];   // [buf][bat][col] = 8 KB

    const int rank = blockIdx.x & 7;
    const int cid  = blockIdx.x >> 3;   // 0..15
    const int tid  = threadIdx.x;
    const int sub  = tid & 7;           // k-range selector
    const int jl   = tid >> 3;          // 0..63 local column
    const int j    = rank * 64 + jl;    // global column 0..511

    // W registers: k = sub*64 + c*4 + {0..3}, c = 0..15, column j
    unsigned long long Wreg[16][2];
#pragma unroll
    for (int c = 0; c < 16; c++) {
        const float* p = Whf + (size_t)(sub * 64 + c * 4) * ND + j;
        float w0 = p[0], w1 = p[ND], w2 = p[2 * ND], w3 = p[3 * ND];
        asm("mov.b64 %0,{%1,%2};" : "=l"(Wreg[c][0]) : "f"(w0), "f"(w1));
        asm("mov.b64 %0,{%1,%2};" : "=l"(Wreg[c][1]) : "f"(w2), "f"(w3));
    }

    // zero h buffers (2048 floats, 512 threads)
    ((float*)hbuf)[tid]        = 0.f;
    ((float*)hbuf)[tid + 512]  = 0.f;
    ((float*)hbuf)[tid + 1024] = 0.f;
    ((float*)hbuf)[tid + 1536] = 0.f;

    const uint32_t hb = (uint32_t)__cvta_generic_to_shared(&hbuf[0][0][0]);

    // producer state (sub == 0 lanes)
    float bj = 0.f, h_prev0 = 0.f, h_prev1 = 0.f;
    const float *nhp0 = nullptr, *ifp0 = nullptr, *nhp1 = nullptr, *ifp1 = nullptr;
    float *hop0 = nullptr, *hop1 = nullptr;
    uint32_t raddr[2][8];   // [buf][rank], for bat 0; bat 1 adds 2048 bytes
    if (sub == 0) {
        bj = bhf[j];
        size_t o0 = (size_t)cid * NT * ND + j;
        size_t o1 = (size_t)(cid + 16) * NT * ND + j;
        nhp0 = nh + o0; ifp0 = ifg + o0; hop0 = hout + o0;
        nhp1 = nh + o1; ifp1 = ifg + o1; hop1 = hout + o1;
#pragma unroll
        for (int buf = 0; buf < 2; buf++) {
            uint32_t la = hb + (uint32_t)((buf * 2 * 512 + j) * 4);
#pragma unroll
            for (int rr = 0; rr < 8; rr++)
                asm("mapa.shared::cluster.u32 %0, %1, %2;"
                    : "=r"(raddr[buf][rr]) : "r"(la), "r"(rr));
        }
    }

    asm volatile("barrier.cluster.arrive.aligned;" ::: "memory");
    asm volatile("barrier.cluster.wait.aligned;"   ::: "memory");

    float nh_c0 = 0.f, if_c0 = 0.f, nh_c1 = 0.f, if_c1 = 0.f;
    if (sub == 0) {
        nh_c0 = nhp0[0]; if_c0 = ifp0[0];
        nh_c1 = nhp1[0]; if_c1 = ifp1[0];
    }

    for (int t = 0; t < NT; t++) {
        const int cur = t & 1, nxt = cur ^ 1;
        // prefetch next step's inputs (long-latency, overlaps compute)
        float nh_n0 = 0.f, if_n0 = 0.f, nh_n1 = 0.f, if_n1 = 0.f;
        if (sub == 0 && t + 1 < NT) {
            size_t off = (size_t)(t + 1) * ND;
            nh_n0 = nhp0[off]; if_n0 = ifp0[off];
            nh_n1 = nhp1[off]; if_n1 = ifp1[off];
        }

#pragma unroll
        for (int bat = 0; bat < 2; bat++) {
            const uint32_t hbase = hb + (uint32_t)(((cur * 2 + bat) * 512 + sub * 64) * 4);
            unsigned long long acc0 = 0ull, acc1 = 0ull;
#pragma unroll
            for (int c = 0; c < 16; c++) {
                unsigned long long h01, h23;
                asm volatile("ld.shared.v2.b64 {%0,%1},[%2];"
                             : "=l"(h01), "=l"(h23) : "r"(hbase + c * 16));
                asm volatile("fma.rn.f32x2 %0, %1, %2, %0;"
                             : "+l"(acc0) : "l"(h01), "l"(Wreg[c][0]));
                asm volatile("fma.rn.f32x2 %0, %1, %2, %0;"
                             : "+l"(acc1) : "l"(h23), "l"(Wreg[c][1]));
            }
            float a0l, a0h, a1l, a1h;
            asm("mov.b64 {%0,%1},%2;" : "=f"(a0l), "=f"(a0h) : "l"(acc0));
            asm("mov.b64 {%0,%1},%2;" : "=f"(a1l), "=f"(a1h) : "l"(acc1));
            float a = (a0l + a0h) + (a1l + a1h);
            a += __shfl_xor_sync(0xffffffffu, a, 1);
            a += __shfl_xor_sync(0xffffffffu, a, 2);
            a += __shfl_xor_sync(0xffffffffu, a, 4);
            if (sub == 0) {
                float if_c = bat ? if_c1 : if_c0;
                float nh_c = bat ? nh_c1 : nh_c0;
                float hp   = bat ? h_prev1 : h_prev0;
                float z = a + bj + if_c;
                float g = 1.f / (1.f + __expf(-z));
                float hn = fmaf(g, nh_c - hp, hp);
                if (bat) { h_prev1 = hn; hop1[(size_t)t * ND] = hn; }
                else     { h_prev0 = hn; hop0[(size_t)t * ND] = hn; }
                const uint32_t boff = (uint32_t)(bat * 2048);
#pragma unroll
                for (int rr = 0; rr < 8; rr++)
                    asm volatile("st.shared::cluster.f32 [%0], %1;"
                                 :: "r"(raddr[nxt][rr] + boff), "f"(hn) : "memory");
            }
        }
        nh_c0 = nh_n0; if_c0 = if_n0;
        nh_c1 = nh_n1; if_c1 = if_n1;
        asm volatile("barrier.cluster.arrive.aligned;" ::: "memory");
        asm volatile("barrier.cluster.wait.aligned;"   ::: "memory");
    }
}

// ---------------- gate cell combine + residual ----------------
__global__ __launch_bounds__(256) void combine_kernel(
    const float4* __restrict__ x,  const float4* __restrict__ xn,
    const float4* __restrict__ nh, const float4* __restrict__ ifb,
    const float4* __restrict__ hf, const float4* __restrict__ bhf,
    float4* __restrict__ out)
{
    size_t idx = (size_t)blockIdx.x * 256 + threadIdx.x;
    float4 xv = x[idx], xnv = xn[idx], nhv = nh[idx], iv = ifb[idx], hv = hf[idx];
    float4 bv = bhf[idx & 127];
    float4 o;
    { float z = hv.x + bv.x + iv.x; float g = 1.f/(1.f+__expf(-z)); o.x = xv.x + xnv.x + g*(nhv.x - xnv.x); }
    { float z = hv.y + bv.y + iv.y; float g = 1.f/(1.f+__expf(-z)); o.y = xv.y + xnv.y + g*(nhv.y - xnv.y); }
    { float z = hv.z + bv.z + iv.z; float g = 1.f/(1.f+__expf(-z)); o.z = xv.z + xnv.z + g*(nhv.z - xnv.z); }
    { float z = hv.w + bv.w + iv.w; float g = 1.f/(1.f+__expf(-z)); o.w = xv.w + xnv.w + g*(nhv.w - xnv.w); }
    out[idx] = o;
}

// ---------------- launch ----------------
static void launch_scan(const float* nh, const float* ifb,
                        const float* W, const float* b, float* ho)
{
    cudaLaunchConfig_t cfg = {};
    cfg.gridDim  = dim3(128, 1, 1);   // 16 clusters x 8 CTAs
    cfg.blockDim = dim3(512, 1, 1);
    cfg.dynamicSmemBytes = 0;
    cfg.stream = 0;
    cudaLaunchAttribute attr;
    attr.id = cudaLaunchAttributeClusterDimension;
    attr.val.clusterDim.x = 8; attr.val.clusterDim.y = 1; attr.val.clusterDim.z = 1;
    cfg.attrs = &attr;
    cfg.numAttrs = 1;
    cudaLaunchKernelEx(&cfg, scan_kernel, nh, ifb, W, b, ho);
}

extern "C" void kernel_launch(void* const* d_in, const int* in_sizes, int n_in,
                              void* d_out, int out_size)
{
    const float* x     = (const float*)d_in[0];
    const float* gamma = (const float*)d_in[1];
    const float* gWn   = (const float*)d_in[2];
    const float* gWif  = (const float*)d_in[3];
    const float* gWhf  = (const float*)d_in[4];
    const float* gbhf  = (const float*)d_in[5];
    const float* l0Wn  = (const float*)d_in[6];
    const float* l0Wif = (const float*)d_in[7];
    const float* l0Whf = (const float*)d_in[8];
    const float* l0bhf = (const float*)d_in[9];
    const float* l1Wn  = (const float*)d_in[10];
    const float* l1Wif = (const float*)d_in[11];
    const float* l1Whf = (const float*)d_in[12];
    const float* l1bhf = (const float*)d_in[13];
    float* out = (float*)d_out;

    float *xn, *nh, *ifb, *hf, *h0, *h1;
    cudaGetSymbolAddress((void**)&xn,  g_xn);
    cudaGetSymbolAddress((void**)&nh,  g_nh);
    cudaGetSymbolAddress((void**)&ifb, g_ifb);
    cudaGetSymbolAddress((void**)&hf,  g_hf);
    cudaGetSymbolAddress((void**)&h0,  g_h0);
    cudaGetSymbolAddress((void**)&h1,  g_h1);

    dim3 gg(NROWS / 128, ND / 128);

    rmsnorm_kernel<<<NROWS / 8, 256>>>(x, gamma, xn);

    sgemm_kernel<1><<<gg, 256>>>(xn, l0Wn,  nh);
    sgemm_kernel<0><<<gg, 256>>>(xn, l0Wif, ifb);
    launch_scan(nh, ifb, l0Whf, l0bhf, h0);

    sgemm_kernel<1><<<gg, 256>>>(h0, l1Wn,  nh);
    sgemm_kernel<0><<<gg, 256>>>(h0, l1Wif, ifb);
    launch_scan(nh, ifb, l1Whf, l1bhf, h1);

    sgemm_kernel<1><<<gg, 256>>>(h1, gWn,  nh);
    sgemm_kernel<0><<<gg, 256>>>(h1, gWif, ifb);
    sgemm_kernel<0><<<gg, 256>>>(xn, gWhf, hf);

    combine_kernel<<<(NROWS * (ND/4)) / 256, 256>>>(
        (const float4*)x, (const float4*)xn, (const float4*)nh,
        (const float4*)ifb, (const float4*)hf, (const float4*)gbhf,
        (float4*)out);
}

// round 8
// speedup vs baseline: 5.3998x; 5.3998x over previous
#include <cuda_runtime.h>
#include <cstdint>
#include <cstddef>

#define NB 32
#define NT 2048
#define ND 512
#define NROWS (NB*NT)   // 65536

// ---------------- scratch (static device arrays; no allocation) ----------------
__device__ float g_xn [(size_t)NROWS*ND];
__device__ float g_nh [(size_t)NROWS*ND];
__device__ float g_ifb[(size_t)NROWS*ND];
__device__ float g_hf [(size_t)NROWS*ND];
__device__ float g_h0 [(size_t)NROWS*ND];
__device__ float g_h1 [(size_t)NROWS*ND];

// ---------------- rmsnorm ----------------
__global__ __launch_bounds__(256) void rmsnorm_kernel(
    const float* __restrict__ x, const float* __restrict__ gamma,
    float* __restrict__ xn)
{
    int row = blockIdx.x * 8 + (threadIdx.x >> 5);
    int l = threadIdx.x & 31;
    const float4* xr = (const float4*)(x + (size_t)row * ND);
    const float4* gp = (const float4*)gamma;
    float4 v[4];
    float ss = 0.f;
#pragma unroll
    for (int i = 0; i < 4; i++) {
        v[i] = xr[l + 32*i];
        ss += v[i].x*v[i].x + v[i].y*v[i].y + v[i].z*v[i].z + v[i].w*v[i].w;
    }
#pragma unroll
    for (int o = 16; o > 0; o >>= 1) ss += __shfl_xor_sync(0xffffffffu, ss, o);
    float n = fmaxf(sqrtf(ss), 1e-12f);
    float s = 22.627416997969522f / n;
    float4* orow = (float4*)(xn + (size_t)row * ND);
#pragma unroll
    for (int i = 0; i < 4; i++) {
        float4 g4 = gp[l + 32*i];
        float4 o;
        o.x = v[i].x * s * (g4.x + 1.f);
        o.y = v[i].y * s * (g4.y + 1.f);
        o.z = v[i].z * s * (g4.z + 1.f);
        o.w = v[i].w * s * (g4.w + 1.f);
        orow[l + 32*i] = o;
    }
}

// ---------------- fp32 SGEMM (proven ~0.85ms): C = A @ W, opt tanh ----------------
template<int ACT>
__global__ __launch_bounds__(256) void sgemm_kernel(
    const float* __restrict__ A, const float* __restrict__ W,
    float* __restrict__ C)
{
    __shared__ float As[8][128];
    __shared__ float Bs[8][128];
    const int tid  = threadIdx.x;
    const int aRow = tid >> 1;
    const int aCol = (tid & 1) * 4;
    const int bRow = tid >> 5;
    const int bCol = (tid & 31) * 4;
    const int tr = tid >> 4;   // 0..15
    const int tc = tid & 15;   // 0..15
    const float* Ap = A + ((size_t)blockIdx.x * 128 + aRow) * ND + aCol;
    const float* Wp = W + (size_t)bRow * ND + blockIdx.y * 128 + bCol;
    float acc[8][8];
#pragma unroll
    for (int i = 0; i < 8; i++)
#pragma unroll
        for (int j = 0; j < 8; j++) acc[i][j] = 0.f;

    for (int k0 = 0; k0 < ND; k0 += 8) {
        float4 a4 = *(const float4*)(Ap + k0);
        float4 b4 = *(const float4*)(Wp + (size_t)k0 * ND);
        As[aCol+0][aRow] = a4.x;
        As[aCol+1][aRow] = a4.y;
        As[aCol+2][aRow] = a4.z;
        As[aCol+3][aRow] = a4.w;
        *(float4*)&Bs[bRow][bCol] = b4;
        __syncthreads();
#pragma unroll
        for (int kk = 0; kk < 8; kk++) {
            float ra[8], rb[8];
#pragma unroll
            for (int i = 0; i < 8; i++) ra[i] = As[kk][tr*8 + i];
#pragma unroll
            for (int j = 0; j < 8; j++) rb[j] = Bs[kk][tc*8 + j];
#pragma unroll
            for (int i = 0; i < 8; i++)
#pragma unroll
                for (int j = 0; j < 8; j++)
                    acc[i][j] = fmaf(ra[i], rb[j], acc[i][j]);
        }
        __syncthreads();
    }

    float* Cp = C + ((size_t)blockIdx.x * 128 + tr*8) * ND + blockIdx.y * 128 + tc*8;
#pragma unroll
    for (int i = 0; i < 8; i++) {
        float vv[8];
#pragma unroll
        for (int j = 0; j < 8; j++) {
            float v = acc[i][j];
            if (ACT == 1) v = tanhf(v);
            vv[j] = v;
        }
        *(float4*)(Cp + (size_t)i * ND)     = make_float4(vv[0], vv[1], vv[2], vv[3]);
        *(float4*)(Cp + (size_t)i * ND + 4) = make_float4(vv[4], vv[5], vv[6], vv[7]);
    }
}

// ---------------- sequential LRU scan, v4 ----------------
// 32 clusters x 4 CTAs (proven topology). CTA owns 128 cols; 4 threads/col,
// k-range 128/thread. W: first 64 k's in fp32 registers (32 b64), last 64 k's
// in smem as PACKED bf16x2 (64KB total, halves crossbar traffic vs fp32).
// fp32 math throughout (bf16 -> f32 via shl/and, exact).
__global__ __launch_bounds__(512, 1) void scan_kernel(
    const float* __restrict__ nh, const float* __restrict__ ifg,
    const float* __restrict__ Whf, const float* __restrict__ bhf,
    float* __restrict__ hout)
{
    extern __shared__ float smem[];   // [0,64KB): bf16 W half; [64KB,+4KB): h double buf
    const int rank  = blockIdx.x & 3;
    const int batch = blockIdx.x >> 2;
    const int tid = threadIdx.x;
    const int sub = tid & 3;
    const int jl  = tid >> 2;
    const int j   = rank * 128 + jl;

    const uint32_t sbase = (uint32_t)__cvta_generic_to_shared(smem);
    const uint32_t hb    = sbase + 65536u;

    // ---- register W half: k = sub*128 + cc*4 + {0..3}, cc = (c + 2*sub)&15 ----
    unsigned long long Wreg[16][2];
#pragma unroll
    for (int c = 0; c < 16; c++) {
        int cc = (c + 2 * sub) & 15;
        const float* p = Whf + (size_t)(sub * 128 + cc * 4) * ND + j;
        float w0 = p[0], w1 = p[ND], w2 = p[2 * ND], w3 = p[3 * ND];
        asm("mov.b64 %0,{%1,%2};" : "=l"(Wreg[c][0]) : "f"(w0), "f"(w1));
        asm("mov.b64 %0,{%1,%2};" : "=l"(Wreg[c][1]) : "f"(w2), "f"(w3));
    }
    // ---- smem W half (bf16x2): superchunk q holds k = sub*128 + 64 + q*8 + {0..7},
    //      stored at slot (q + jl)&7 within this thread's 128B block ----
#pragma unroll
    for (int q = 0; q < 8; q++) {
        const float* p = Whf + (size_t)(sub * 128 + 64 + q * 8) * ND + j;
        float w0=p[0], w1=p[ND], w2=p[2*ND], w3=p[3*ND];
        float w4=p[4*ND], w5=p[5*ND], w6=p[6*ND], w7=p[7*ND];
        uint32_t u0, u1, u2, u3;
        asm("cvt.rn.bf16x2.f32 %0, %1, %2;" : "=r"(u0) : "f"(w1), "f"(w0));
        asm("cvt.rn.bf16x2.f32 %0, %1, %2;" : "=r"(u1) : "f"(w3), "f"(w2));
        asm("cvt.rn.bf16x2.f32 %0, %1, %2;" : "=r"(u2) : "f"(w5), "f"(w4));
        asm("cvt.rn.bf16x2.f32 %0, %1, %2;" : "=r"(u3) : "f"(w7), "f"(w6));
        uint32_t wa = sbase + (uint32_t)(tid * 128 + ((q + jl) & 7) * 16);
        asm volatile("st.shared.v4.b32 [%0], {%1,%2,%3,%4};"
                     :: "r"(wa), "r"(u0), "r"(u1), "r"(u2), "r"(u3) : "memory");
    }
    float* hbuf = (float*)((char*)smem + 65536);
    hbuf[tid] = 0.f;
    hbuf[tid + 512] = 0.f;

    float bj = 0.f, h_prev = 0.f;
    const float *nhp = nullptr, *ifp = nullptr;
    float* hop = nullptr;
    uint32_t raddr[2][4];
    if (sub == 0) {
        bj = bhf[j];
        size_t off = (size_t)batch * NT * ND + j;
        nhp = nh + off; ifp = ifg + off; hop = hout + off;
#pragma unroll
        for (int buf = 0; buf < 2; buf++) {
            uint32_t la = hb + (uint32_t)((buf * 512 + j) * 4);
#pragma unroll
            for (int rr = 0; rr < 4; rr++)
                asm("mapa.shared::cluster.u32 %0, %1, %2;"
                    : "=r"(raddr[buf][rr]) : "r"(la), "r"(rr));
        }
    }

    asm volatile("barrier.cluster.arrive.aligned;" ::: "memory");
    asm volatile("barrier.cluster.wait.aligned;"   ::: "memory");

    float nh_cur = 0.f, if_cur = 0.f;
    if (sub == 0) { nh_cur = nhp[0]; if_cur = ifp[0]; }

    const uint32_t wbase = sbase + (uint32_t)(tid * 128);

    for (int t = 0; t < NT; t++) {
        const uint32_t hcur = hb + ((uint32_t)(t & 1) << 11);
        float nh_nxt = 0.f, if_nxt = 0.f;
        if (sub == 0 && t + 1 < NT) {
            nh_nxt = nhp[(size_t)(t + 1) * ND];
            if_nxt = ifp[(size_t)(t + 1) * ND];
        }
        unsigned long long acc0 = 0ull, acc1 = 0ull;
        // register half
        const uint32_t h1base = hcur + (uint32_t)(sub * 512);
#pragma unroll
        for (int c = 0; c < 16; c++) {
            int cc = (c + 2 * sub) & 15;
            unsigned long long h01, h23;
            asm volatile("ld.shared.v2.b64 {%0,%1},[%2];"
                         : "=l"(h01), "=l"(h23) : "r"(h1base + cc * 16));
            asm volatile("fma.rn.f32x2 %0, %1, %2, %0;" : "+l"(acc0) : "l"(h01), "l"(Wreg[c][0]));
            asm volatile("fma.rn.f32x2 %0, %1, %2, %0;" : "+l"(acc1) : "l"(h23), "l"(Wreg[c][1]));
        }
        // smem half (bf16 W)
        const uint32_t h2base = h1base + 256u;
#pragma unroll
        for (int qp = 0; qp < 8; qp++) {
            int q = (qp + sub) & 7;
            unsigned long long h01, h23, h45, h67;
            uint32_t u0, u1, u2, u3;
            asm volatile("ld.shared.v2.b64 {%0,%1},[%2];"
                         : "=l"(h01), "=l"(h23) : "r"(h2base + q * 32));
            asm volatile("ld.shared.v2.b64 {%0,%1},[%2];"
                         : "=l"(h45), "=l"(h67) : "r"(h2base + q * 32 + 16));
            asm volatile("ld.shared.v4.b32 {%0,%1,%2,%3},[%4];"
                         : "=r"(u0), "=r"(u1), "=r"(u2), "=r"(u3)
                         : "r"(wbase + ((q + jl) & 7) * 16));
            unsigned long long w01, w23, w45, w67;
            asm("{.reg .b32 lo,hi; shl.b32 lo,%1,16; and.b32 hi,%1,0xffff0000U; mov.b64 %0,{lo,hi};}"
                : "=l"(w01) : "r"(u0));
            asm("{.reg .b32 lo,hi; shl.b32 lo,%1,16; and.b32 hi,%1,0xffff0000U; mov.b64 %0,{lo,hi};}"
                : "=l"(w23) : "r"(u1));
            asm("{.reg .b32 lo,hi; shl.b32 lo,%1,16; and.b32 hi,%1,0xffff0000U; mov.b64 %0,{lo,hi};}"
                : "=l"(w45) : "r"(u2));
            asm("{.reg .b32 lo,hi; shl.b32 lo,%1,16; and.b32 hi,%1,0xffff0000U; mov.b64 %0,{lo,hi};}"
                : "=l"(w67) : "r"(u3));
            asm volatile("fma.rn.f32x2 %0, %1, %2, %0;" : "+l"(acc0) : "l"(h01), "l"(w01));
            asm volatile("fma.rn.f32x2 %0, %1, %2, %0;" : "+l"(acc1) : "l"(h23), "l"(w23));
            asm volatile("fma.rn.f32x2 %0, %1, %2, %0;" : "+l"(acc0) : "l"(h45), "l"(w45));
            asm volatile("fma.rn.f32x2 %0, %1, %2, %0;" : "+l"(acc1) : "l"(h67), "l"(w67));
        }
        float a0l, a0h, a1l, a1h;
        asm("mov.b64 {%0,%1},%2;" : "=f"(a0l), "=f"(a0h) : "l"(acc0));
        asm("mov.b64 {%0,%1},%2;" : "=f"(a1l), "=f"(a1h) : "l"(acc1));
        float a = (a0l + a0h) + (a1l + a1h);
        a += __shfl_xor_sync(0xffffffffu, a, 1);
        a += __shfl_xor_sync(0xffffffffu, a, 2);
        if (sub == 0) {
            float z = a + bj + if_cur;
            float g = 1.f / (1.f + __expf(-z));
            float hn = fmaf(g, nh_cur - h_prev, h_prev);
            hop[(size_t)t * ND] = hn;
            h_prev = hn;
            const int nb = (t + 1) & 1;
            asm volatile("st.shared::cluster.f32 [%0], %1;" :: "r"(raddr[nb][0]), "f"(hn) : "memory");
            asm volatile("st.shared::cluster.f32 [%0], %1;" :: "r"(raddr[nb][1]), "f"(hn) : "memory");
            asm volatile("st.shared::cluster.f32 [%0], %1;" :: "r"(raddr[nb][2]), "f"(hn) : "memory");
            asm volatile("st.shared::cluster.f32 [%0], %1;" :: "r"(raddr[nb][3]), "f"(hn) : "memory");
        }
        nh_cur = nh_nxt; if_cur = if_nxt;
        asm volatile("barrier.cluster.arrive.aligned;" ::: "memory");
        asm volatile("barrier.cluster.wait.aligned;"   ::: "memory");
    }
}

// ---------------- gate cell combine + residual ----------------
__global__ __launch_bounds__(256) void combine_kernel(
    const float4* __restrict__ x,  const float4* __restrict__ xn,
    const float4* __restrict__ nh, const float4* __restrict__ ifb,
    const float4* __restrict__ hf, const float4* __restrict__ bhf,
    float4* __restrict__ out)
{
    size_t idx = (size_t)blockIdx.x * 256 + threadIdx.x;
    float4 xv = x[idx], xnv = xn[idx], nhv = nh[idx], iv = ifb[idx], hv = hf[idx];
    float4 bv = bhf[idx & 127];
    float4 o;
    { float z = hv.x + bv.x + iv.x; float g = 1.f/(1.f+__expf(-z)); o.x = xv.x + xnv.x + g*(nhv.x - xnv.x); }
    { float z = hv.y + bv.y + iv.y; float g = 1.f/(1.f+__expf(-z)); o.y = xv.y + xnv.y + g*(nhv.y - xnv.y); }
    { float z = hv.z + bv.z + iv.z; float g = 1.f/(1.f+__expf(-z)); o.z = xv.z + xnv.z + g*(nhv.z - xnv.z); }
    { float z = hv.w + bv.w + iv.w; float g = 1.f/(1.f+__expf(-z)); o.w = xv.w + xnv.w + g*(nhv.w - xnv.w); }
    out[idx] = o;
}

// ---------------- launch ----------------
static void launch_scan(const float* nh, const float* ifb,
                        const float* W, const float* b, float* ho)
{
    constexpr int SMEMB = 65536 + 4096;   // bf16 W half + h double buffer
    cudaFuncSetAttribute(scan_kernel, cudaFuncAttributeMaxDynamicSharedMemorySize, SMEMB);
    cudaLaunchConfig_t cfg = {};
    cfg.gridDim  = dim3(128, 1, 1);   // 32 clusters x 4 CTAs
    cfg.blockDim = dim3(512, 1, 1);
    cfg.dynamicSmemBytes = SMEMB;
    cfg.stream = 0;
    cudaLaunchAttribute attr;
    attr.id = cudaLaunchAttributeClusterDimension;
    attr.val.clusterDim.x = 4; attr.val.clusterDim.y = 1; attr.val.clusterDim.z = 1;
    cfg.attrs = &attr;
    cfg.numAttrs = 1;
    cudaLaunchKernelEx(&cfg, scan_kernel, nh, ifb, W, b, ho);
}

extern "C" void kernel_launch(void* const* d_in, const int* in_sizes, int n_in,
                              void* d_out, int out_size)
{
    const float* x     = (const float*)d_in[0];
    const float* gamma = (const float*)d_in[1];
    const float* gWn   = (const float*)d_in[2];
    const float* gWif  = (const float*)d_in[3];
    const float* gWhf  = (const float*)d_in[4];
    const float* gbhf  = (const float*)d_in[5];
    const float* l0Wn  = (const float*)d_in[6];
    const float* l0Wif = (const float*)d_in[7];
    const float* l0Whf = (const float*)d_in[8];
    const float* l0bhf = (const float*)d_in[9];
    const float* l1Wn  = (const float*)d_in[10];
    const float* l1Wif = (const float*)d_in[11];
    const float* l1Whf = (const float*)d_in[12];
    const float* l1bhf = (const float*)d_in[13];
    float* out = (float*)d_out;

    float *xn, *nh, *ifb, *hf, *h0, *h1;
    cudaGetSymbolAddress((void**)&xn,  g_xn);
    cudaGetSymbolAddress((void**)&nh,  g_nh);
    cudaGetSymbolAddress((void**)&ifb, g_ifb);
    cudaGetSymbolAddress((void**)&hf,  g_hf);
    cudaGetSymbolAddress((void**)&h0,  g_h0);
    cudaGetSymbolAddress((void**)&h1,  g_h1);

    dim3 gg(NROWS / 128, ND / 128);

    rmsnorm_kernel<<<NROWS / 8, 256>>>(x, gamma, xn);

    sgemm_kernel<1><<<gg, 256>>>(xn, l0Wn,  nh);
    sgemm_kernel<0><<<gg, 256>>>(xn, l0Wif, ifb);
    launch_scan(nh, ifb, l0Whf, l0bhf, h0);

    sgemm_kernel<1><<<gg, 256>>>(h0, l1Wn,  nh);
    sgemm_kernel<0><<<gg, 256>>>(h0, l1Wif, ifb);
    launch_scan(nh, ifb, l1Whf, l1bhf, h1);

    sgemm_kernel<1><<<gg, 256>>>(h1, gWn,  nh);
    sgemm_kernel<0><<<gg, 256>>>(h1, gWif, ifb);
    sgemm_kernel<0><<<gg, 256>>>(xn, gWhf, hf);

    combine_kernel<<<(NROWS * (ND/4)) / 256, 256>>>(
        (const float4*)x, (const float4*)xn, (const float4*)nh,
        (const float4*)ifb, (const float4*)hf, (const float4*)gbhf,
        (float4*)out);
}

// round 9
// speedup vs baseline: 8.4545x; 1.5657x over previous
#include <cuda_runtime.h>
#include <cstdint>
#include <cstddef>

#define NB 32
#define NT 2048
#define ND 512
#define NROWS (NB*NT)   // 65536

// ---------------- scratch (static device arrays; no allocation) ----------------
__device__ float g_xn [(size_t)NROWS*ND];
__device__ float g_nh [(size_t)NROWS*ND];
__device__ float g_ifb[(size_t)NROWS*ND];
__device__ float g_hf [(size_t)NROWS*ND];
__device__ float g_h0 [(size_t)NROWS*ND];
__device__ float g_h1 [(size_t)NROWS*ND];

// ---------------- rmsnorm ----------------
__global__ __launch_bounds__(256) void rmsnorm_kernel(
    const float* __restrict__ x, const float* __restrict__ gamma,
    float* __restrict__ xn)
{
    int row = blockIdx.x * 8 + (threadIdx.x >> 5);
    int l = threadIdx.x & 31;
    const float4* xr = (const float4*)(x + (size_t)row * ND);
    const float4* gp = (const float4*)gamma;
    float4 v[4];
    float ss = 0.f;
#pragma unroll
    for (int i = 0; i < 4; i++) {
        v[i] = xr[l + 32*i];
        ss += v[i].x*v[i].x + v[i].y*v[i].y + v[i].z*v[i].z + v[i].w*v[i].w;
    }
#pragma unroll
    for (int o = 16; o > 0; o >>= 1) ss += __shfl_xor_sync(0xffffffffu, ss, o);
    float n = fmaxf(sqrtf(ss), 1e-12f);
    float s = 22.627416997969522f / n;
    float4* orow = (float4*)(xn + (size_t)row * ND);
#pragma unroll
    for (int i = 0; i < 4; i++) {
        float4 g4 = gp[l + 32*i];
        float4 o;
        o.x = v[i].x * s * (g4.x + 1.f);
        o.y = v[i].y * s * (g4.y + 1.f);
        o.z = v[i].z * s * (g4.z + 1.f);
        o.w = v[i].w * s * (g4.w + 1.f);
        orow[l + 32*i] = o;
    }
}

// ---------------- tf32 tensor-core GEMM (R2 proven, ~0.36ms): C = A @ W ----------------
// BM=BN=128, BK=16, 256 threads (8 warps, 4x2), warp tile 32x64 via m16n8k8 tf32 mma.
__device__ __forceinline__ uint32_t f2tf(float f) {
    uint32_t u; asm("cvt.rna.tf32.f32 %0, %1;" : "=r"(u) : "f"(f)); return u;
}
__device__ __forceinline__ void mma1688(float c[4], const uint32_t a[4], const uint32_t b[2]) {
    asm volatile(
        "mma.sync.aligned.m16n8k8.row.col.f32.tf32.tf32.f32 "
        "{%0,%1,%2,%3},{%4,%5,%6,%7},{%8,%9},{%0,%1,%2,%3};"
        : "+f"(c[0]), "+f"(c[1]), "+f"(c[2]), "+f"(c[3])
        : "r"(a[0]), "r"(a[1]), "r"(a[2]), "r"(a[3]), "r"(b[0]), "r"(b[1]));
}

template<int ACT>
__global__ __launch_bounds__(256) void tgemm_kernel(
    const float* __restrict__ A, const float* __restrict__ W,
    float* __restrict__ C)
{
    __shared__ uint32_t As[2][16][136];
    __shared__ uint32_t Bs[2][16][136];
    const int tid = threadIdx.x;
    const int l   = tid & 31;
    const int wid = tid >> 5;
    const int wm  = wid & 3;    // 0..3 -> 32-row stripes
    const int wn  = wid >> 2;   // 0..1 -> 64-col stripes
    const int gid = l >> 2, tig = l & 3;

    const int am = tid >> 1;          // 0..127
    const int ak = (tid & 1) * 8;     // 0 or 8
    const int bk = tid >> 5;          // 0..7
    const int bn = (tid & 31) * 4;

    const float* Ap = A + ((size_t)blockIdx.x * 128 + am) * ND + ak;
    const float* Wp = W + (size_t)bk * ND + blockIdx.y * 128 + bn;

    float acc[2][8][4];
#pragma unroll
    for (int mt = 0; mt < 2; mt++)
#pragma unroll
        for (int nt = 0; nt < 8; nt++)
#pragma unroll
            for (int e = 0; e < 4; e++) acc[mt][nt][e] = 0.f;

    float4 pa0 = *(const float4*)(Ap);
    float4 pa1 = *(const float4*)(Ap + 4);
    float4 pb0 = *(const float4*)(Wp);
    float4 pb1 = *(const float4*)(Wp + (size_t)8 * ND);

    // store stage 0
    {
        As[0][ak+0][am] = f2tf(pa0.x); As[0][ak+1][am] = f2tf(pa0.y);
        As[0][ak+2][am] = f2tf(pa0.z); As[0][ak+3][am] = f2tf(pa0.w);
        As[0][ak+4][am] = f2tf(pa1.x); As[0][ak+5][am] = f2tf(pa1.y);
        As[0][ak+6][am] = f2tf(pa1.z); As[0][ak+7][am] = f2tf(pa1.w);
        uint4 u0 = make_uint4(f2tf(pb0.x), f2tf(pb0.y), f2tf(pb0.z), f2tf(pb0.w));
        uint4 u1 = make_uint4(f2tf(pb1.x), f2tf(pb1.y), f2tf(pb1.z), f2tf(pb1.w));
        *(uint4*)&Bs[0][bk][bn]     = u0;
        *(uint4*)&Bs[0][bk + 8][bn] = u1;
    }
    __syncthreads();

    for (int kt = 0; kt < 32; kt++) {
        const int cur = kt & 1;
        if (kt < 31) {
            const int k0 = (kt + 1) * 16;
            pa0 = *(const float4*)(Ap + k0);
            pa1 = *(const float4*)(Ap + k0 + 4);
            pb0 = *(const float4*)(Wp + (size_t)k0 * ND);
            pb1 = *(const float4*)(Wp + (size_t)(k0 + 8) * ND);
        }
#pragma unroll
        for (int ks = 0; ks < 16; ks += 8) {
            uint32_t af[2][4], bf[8][2];
#pragma unroll
            for (int mt = 0; mt < 2; mt++) {
                int m0 = wm * 32 + mt * 16 + gid;
                af[mt][0] = As[cur][ks + tig][m0];
                af[mt][1] = As[cur][ks + tig][m0 + 8];
                af[mt][2] = As[cur][ks + tig + 4][m0];
                af[mt][3] = As[cur][ks + tig + 4][m0 + 8];
            }
#pragma unroll
            for (int nt = 0; nt < 8; nt++) {
                int n0 = wn * 64 + nt * 8 + gid;
                bf[nt][0] = Bs[cur][ks + tig][n0];
                bf[nt][1] = Bs[cur][ks + tig + 4][n0];
            }
#pragma unroll
            for (int mt = 0; mt < 2; mt++)
#pragma unroll
                for (int nt = 0; nt < 8; nt++)
                    mma1688(acc[mt][nt], af[mt], bf[nt]);
        }
        if (kt < 31) {
            const int nxt = cur ^ 1;
            As[nxt][ak+0][am] = f2tf(pa0.x); As[nxt][ak+1][am] = f2tf(pa0.y);
            As[nxt][ak+2][am] = f2tf(pa0.z); As[nxt][ak+3][am] = f2tf(pa0.w);
            As[nxt][ak+4][am] = f2tf(pa1.x); As[nxt][ak+5][am] = f2tf(pa1.y);
            As[nxt][ak+6][am] = f2tf(pa1.z); As[nxt][ak+7][am] = f2tf(pa1.w);
            uint4 u0 = make_uint4(f2tf(pb0.x), f2tf(pb0.y), f2tf(pb0.z), f2tf(pb0.w));
            uint4 u1 = make_uint4(f2tf(pb1.x), f2tf(pb1.y), f2tf(pb1.z), f2tf(pb1.w));
            *(uint4*)&Bs[nxt][bk][bn]     = u0;
            *(uint4*)&Bs[nxt][bk + 8][bn] = u1;
        }
        __syncthreads();
    }

    // epilogue
#pragma unroll
    for (int mt = 0; mt < 2; mt++) {
        int row = blockIdx.x * 128 + wm * 32 + mt * 16 + gid;
#pragma unroll
        for (int nt = 0; nt < 8; nt++) {
            int col = blockIdx.y * 128 + wn * 64 + nt * 8 + tig * 2;
            float v0 = acc[mt][nt][0], v1 = acc[mt][nt][1];
            float v2 = acc[mt][nt][2], v3 = acc[mt][nt][3];
            if (ACT == 1) { v0 = tanhf(v0); v1 = tanhf(v1); v2 = tanhf(v2); v3 = tanhf(v3); }
            *(float2*)(C + (size_t)row * ND + col)       = make_float2(v0, v1);
            *(float2*)(C + (size_t)(row + 8) * ND + col) = make_float2(v2, v3);
        }
    }
}

// ---------------- sequential LRU scan (R1 original — fastest measured variant) ----------------
__device__ __forceinline__ uint32_t swz256(uint32_t o) { return o ^ ((o >> 4) & 0x70u); }

__global__ __launch_bounds__(512, 1) void scan_kernel(
    const float* __restrict__ nh, const float* __restrict__ ifg,
    const float* __restrict__ Whf, const float* __restrict__ bhf,
    float* __restrict__ hout)
{
    extern __shared__ float smem[];
    char*  wsm  = (char*)smem;          // 512 threads * 256 B = 131072 B
    float* hbuf = smem + 32768;         // 2 x 512 floats (double buffer)

    const int rank  = blockIdx.x & 3;
    const int batch = blockIdx.x >> 2;
    const int tid = threadIdx.x;
    const int w = tid >> 5;
    const int l = tid & 31;
    const int jc = rank * 128 + w * 8;  // this warp's 8 global columns

    // registers: k = l + 32*i, i = 0..7  (k < 256)
    float Wreg[8][8];
#pragma unroll
    for (int i = 0; i < 8; i++) {
        const float* p = Whf + (size_t)(l + 32*i) * ND + jc;
        float4 a = *(const float4*)p;
        float4 b = *(const float4*)(p + 4);
        Wreg[i][0]=a.x; Wreg[i][1]=a.y; Wreg[i][2]=a.z; Wreg[i][3]=a.w;
        Wreg[i][4]=b.x; Wreg[i][5]=b.y; Wreg[i][6]=b.z; Wreg[i][7]=b.w;
    }
    // smem: k = 256 + l + 32*i, i = 0..7; per-thread 256B block, swizzled
    const uint32_t base = (uint32_t)tid * 256u;
#pragma unroll
    for (int i = 0; i < 8; i++) {
        const float* p = Whf + (size_t)(256 + l + 32*i) * ND + jc;
        float4 a = *(const float4*)p;
        float4 b = *(const float4*)(p + 4);
        *(float4*)(wsm + swz256(base + i*32u))       = a;
        *(float4*)(wsm + swz256(base + i*32u + 16u)) = b;
    }
    hbuf[tid] = 0.f;
    hbuf[tid + 512] = 0.f;

    float bj = 0.f;
    const float *nhp = nullptr, *ifp = nullptr;
    float* hop = nullptr;
    const int j = jc + l;   // only meaningful for l < 8
    if (l < 8) {
        bj = bhf[j];
        size_t off = (size_t)batch * NT * ND + j;
        nhp = nh + off; ifp = ifg + off; hop = hout + off;
    }
    const uint32_t hbase = (uint32_t)__cvta_generic_to_shared(hbuf);

    asm volatile("barrier.cluster.arrive.aligned;\n" ::: "memory");
    asm volatile("barrier.cluster.wait.aligned;\n"   ::: "memory");

    float nh_cur = 0.f, if_cur = 0.f;
    if (l < 8) { nh_cur = nhp[0]; if_cur = ifp[0]; }

    for (int t = 0; t < NT; t++) {
        const float* hr = hbuf + (t & 1) * 512;
        // prefetch next step's inputs
        float nh_nxt = 0.f, if_nxt = 0.f;
        if (l < 8 && t + 1 < NT) {
            nh_nxt = nhp[(size_t)(t+1) * ND];
            if_nxt = ifp[(size_t)(t+1) * ND];
        }
        float acc[8] = {0,0,0,0,0,0,0,0};
#pragma unroll
        for (int i = 0; i < 8; i++) {
            float hk = hr[l + 32*i];
#pragma unroll
            for (int c = 0; c < 8; c++) acc[c] = fmaf(hk, Wreg[i][c], acc[c]);
        }
#pragma unroll
        for (int i = 0; i < 8; i++) {
            float hk = hr[256 + l + 32*i];
            float4 a = *(const float4*)(wsm + swz256(base + i*32u));
            float4 b = *(const float4*)(wsm + swz256(base + i*32u + 16u));
            acc[0]=fmaf(hk,a.x,acc[0]); acc[1]=fmaf(hk,a.y,acc[1]);
            acc[2]=fmaf(hk,a.z,acc[2]); acc[3]=fmaf(hk,a.w,acc[3]);
            acc[4]=fmaf(hk,b.x,acc[4]); acc[5]=fmaf(hk,b.y,acc[5]);
            acc[6]=fmaf(hk,b.z,acc[6]); acc[7]=fmaf(hk,b.w,acc[7]);
        }
#pragma unroll
        for (int c = 0; c < 8; c++) {
#pragma unroll
            for (int o = 16; o > 0; o >>= 1)
                acc[c] += __shfl_xor_sync(0xffffffffu, acc[c], o);
        }
        if (l < 8) {
            float av = acc[0];
#pragma unroll
            for (int c = 1; c < 8; c++) av = (l == c) ? acc[c] : av;
            float z  = av + bj + if_cur;
            float g  = 1.f / (1.f + __expf(-z));
            float hj = hr[j];
            float hn = fmaf(g, nh_cur - hj, hj);
            hop[(size_t)t * ND] = hn;
            uint32_t laddr = hbase + (uint32_t)((((t + 1) & 1) * 512 + j) * 4);
#pragma unroll
            for (int rr = 0; rr < 4; rr++) {
                uint32_t ra;
                asm volatile("mapa.shared::cluster.u32 %0, %1, %2;"
                             : "=r"(ra) : "r"(laddr), "r"(rr));
                asm volatile("st.shared::cluster.f32 [%0], %1;"
                             :: "r"(ra), "f"(hn) : "memory");
            }
        }
        nh_cur = nh_nxt; if_cur = if_nxt;
        asm volatile("barrier.cluster.arrive.aligned;\n" ::: "memory");
        asm volatile("barrier.cluster.wait.aligned;\n"   ::: "memory");
    }
}

// ---------------- gate cell combine + residual ----------------
__global__ __launch_bounds__(256) void combine_kernel(
    const float4* __restrict__ x,  const float4* __restrict__ xn,
    const float4* __restrict__ nh, const float4* __restrict__ ifb,
    const float4* __restrict__ hf, const float4* __restrict__ bhf,
    float4* __restrict__ out)
{
    size_t idx = (size_t)blockIdx.x * 256 + threadIdx.x;
    float4 xv = x[idx], xnv = xn[idx], nhv = nh[idx], iv = ifb[idx], hv = hf[idx];
    float4 bv = bhf[idx & 127];
    float4 o;
    { float z = hv.x + bv.x + iv.x; float g = 1.f/(1.f+__expf(-z)); o.x = xv.x + xnv.x + g*(nhv.x - xnv.x); }
    { float z = hv.y + bv.y + iv.y; float g = 1.f/(1.f+__expf(-z)); o.y = xv.y + xnv.y + g*(nhv.y - xnv.y); }
    { float z = hv.z + bv.z + iv.z; float g = 1.f/(1.f+__expf(-z)); o.z = xv.z + xnv.z + g*(nhv.z - xnv.z); }
    { float z = hv.w + bv.w + iv.w; float g = 1.f/(1.f+__expf(-z)); o.w = xv.w + xnv.w + g*(nhv.w - xnv.w); }
    out[idx] = o;
}

// ---------------- launch ----------------
static void launch_scan(const float* nh, const float* ifb,
                        const float* W, const float* b, float* ho)
{
    constexpr int SMEMB = 512*256 + 2*512*4;   // 135168 B
    cudaFuncSetAttribute(scan_kernel, cudaFuncAttributeMaxDynamicSharedMemorySize, SMEMB);
    cudaLaunchConfig_t cfg = {};
    cfg.gridDim  = dim3(128, 1, 1);
    cfg.blockDim = dim3(512, 1, 1);
    cfg.dynamicSmemBytes = SMEMB;
    cfg.stream = 0;
    cudaLaunchAttribute attr;
    attr.id = cudaLaunchAttributeClusterDimension;
    attr.val.clusterDim.x = 4; attr.val.clusterDim.y = 1; attr.val.clusterDim.z = 1;
    cfg.attrs = &attr;
    cfg.numAttrs = 1;
    cudaLaunchKernelEx(&cfg, scan_kernel, nh, ifb, W, b, ho);
}

extern "C" void kernel_launch(void* const* d_in, const int* in_sizes, int n_in,
                              void* d_out, int out_size)
{
    const float* x     = (const float*)d_in[0];
    const float* gamma = (const float*)d_in[1];
    const float* gWn   = (const float*)d_in[2];
    const float* gWif  = (const float*)d_in[3];
    const float* gWhf  = (const float*)d_in[4];
    const float* gbhf  = (const float*)d_in[5];
    const float* l0Wn  = (const float*)d_in[6];
    const float* l0Wif = (const float*)d_in[7];
    const float* l0Whf = (const float*)d_in[8];
    const float* l0bhf = (const float*)d_in[9];
    const float* l1Wn  = (const float*)d_in[10];
    const float* l1Wif = (const float*)d_in[11];
    const float* l1Whf = (const float*)d_in[12];
    const float* l1bhf = (const float*)d_in[13];
    float* out = (float*)d_out;

    float *xn, *nh, *ifb, *hf, *h0, *h1;
    cudaGetSymbolAddress((void**)&xn,  g_xn);
    cudaGetSymbolAddress((void**)&nh,  g_nh);
    cudaGetSymbolAddress((void**)&ifb, g_ifb);
    cudaGetSymbolAddress((void**)&hf,  g_hf);
    cudaGetSymbolAddress((void**)&h0,  g_h0);
    cudaGetSymbolAddress((void**)&h1,  g_h1);

    dim3 gg(NROWS / 128, ND / 128);

    rmsnorm_kernel<<<NROWS / 8, 256>>>(x, gamma, xn);

    tgemm_kernel<1><<<gg, 256>>>(xn, l0Wn,  nh);
    tgemm_kernel<0><<<gg, 256>>>(xn, l0Wif, ifb);
    launch_scan(nh, ifb, l0Whf, l0bhf, h0);

    tgemm_kernel<1><<<gg, 256>>>(h0, l1Wn,  nh);
    tgemm_kernel<0><<<gg, 256>>>(h0, l1Wif, ifb);
    launch_scan(nh, ifb, l1Whf, l1bhf, h1);

    tgemm_kernel<1><<<gg, 256>>>(h1, gWn,  nh);
    tgemm_kernel<0><<<gg, 256>>>(h1, gWif, ifb);
    tgemm_kernel<0><<<gg, 256>>>(xn, gWhf, hf);

    combine_kernel<<<(NROWS * (ND/4)) / 256, 256>>>(
        (const float4*)x, (const float4*)xn, (const float4*)nh,
        (const float4*)ifb, (const float4*)hf, (const float4*)gbhf,
        (float4*)out);
}

// round 10
// speedup vs baseline: 10.6862x; 1.2640x over previous
#include <cuda_runtime.h>
#include <cstdint>
#include <cstddef>

#define NB 32
#define NT 2048
#define ND 512
#define NROWS (NB*NT)   // 65536

// ---------------- scratch (static device arrays; no allocation) ----------------
__device__ float g_xn [(size_t)NROWS*ND];
__device__ float g_nh [(size_t)NROWS*ND];
__device__ float g_ifb[(size_t)NROWS*ND];
__device__ float g_hf [(size_t)NROWS*ND];
__device__ float g_h0 [(size_t)NROWS*ND];
__device__ float g_h1 [(size_t)NROWS*ND];

// ---------------- rmsnorm ----------------
__global__ __launch_bounds__(256) void rmsnorm_kernel(
    const float* __restrict__ x, const float* __restrict__ gamma,
    float* __restrict__ xn)
{
    int row = blockIdx.x * 8 + (threadIdx.x >> 5);
    int l = threadIdx.x & 31;
    const float4* xr = (const float4*)(x + (size_t)row * ND);
    const float4* gp = (const float4*)gamma;
    float4 v[4];
    float ss = 0.f;
#pragma unroll
    for (int i = 0; i < 4; i++) {
        v[i] = xr[l + 32*i];
        ss += v[i].x*v[i].x + v[i].y*v[i].y + v[i].z*v[i].z + v[i].w*v[i].w;
    }
#pragma unroll
    for (int o = 16; o > 0; o >>= 1) ss += __shfl_xor_sync(0xffffffffu, ss, o);
    float n = fmaxf(sqrtf(ss), 1e-12f);
    float s = 22.627416997969522f / n;
    float4* orow = (float4*)(xn + (size_t)row * ND);
#pragma unroll
    for (int i = 0; i < 4; i++) {
        float4 g4 = gp[l + 32*i];
        float4 o;
        o.x = v[i].x * s * (g4.x + 1.f);
        o.y = v[i].y * s * (g4.y + 1.f);
        o.z = v[i].z * s * (g4.z + 1.f);
        o.w = v[i].w * s * (g4.w + 1.f);
        orow[l + 32*i] = o;
    }
}

// ---------------- tf32 tensor-core GEMM (proven ~0.36ms): C = A @ W ----------------
__device__ __forceinline__ uint32_t f2tf(float f) {
    uint32_t u; asm("cvt.rna.tf32.f32 %0, %1;" : "=r"(u) : "f"(f)); return u;
}
__device__ __forceinline__ void mma1688(float c[4], const uint32_t a[4], const uint32_t b[2]) {
    asm volatile(
        "mma.sync.aligned.m16n8k8.row.col.f32.tf32.tf32.f32 "
        "{%0,%1,%2,%3},{%4,%5,%6,%7},{%8,%9},{%0,%1,%2,%3};"
        : "+f"(c[0]), "+f"(c[1]), "+f"(c[2]), "+f"(c[3])
        : "r"(a[0]), "r"(a[1]), "r"(a[2]), "r"(a[3]), "r"(b[0]), "r"(b[1]));
}

template<int ACT>
__global__ __launch_bounds__(256) void tgemm_kernel(
    const float* __restrict__ A, const float* __restrict__ W,
    float* __restrict__ C)
{
    __shared__ uint32_t As[2][16][136];
    __shared__ uint32_t Bs[2][16][136];
    const int tid = threadIdx.x;
    const int l   = tid & 31;
    const int wid = tid >> 5;
    const int wm  = wid & 3;
    const int wn  = wid >> 2;
    const int gid = l >> 2, tig = l & 3;

    const int am = tid >> 1;
    const int ak = (tid & 1) * 8;
    const int bk = tid >> 5;
    const int bn = (tid & 31) * 4;

    const float* Ap = A + ((size_t)blockIdx.x * 128 + am) * ND + ak;
    const float* Wp = W + (size_t)bk * ND + blockIdx.y * 128 + bn;

    float acc[2][8][4];
#pragma unroll
    for (int mt = 0; mt < 2; mt++)
#pragma unroll
        for (int nt = 0; nt < 8; nt++)
#pragma unroll
            for (int e = 0; e < 4; e++) acc[mt][nt][e] = 0.f;

    float4 pa0 = *(const float4*)(Ap);
    float4 pa1 = *(const float4*)(Ap + 4);
    float4 pb0 = *(const float4*)(Wp);
    float4 pb1 = *(const float4*)(Wp + (size_t)8 * ND);

    {
        As[0][ak+0][am] = f2tf(pa0.x); As[0][ak+1][am] = f2tf(pa0.y);
        As[0][ak+2][am] = f2tf(pa0.z); As[0][ak+3][am] = f2tf(pa0.w);
        As[0][ak+4][am] = f2tf(pa1.x); As[0][ak+5][am] = f2tf(pa1.y);
        As[0][ak+6][am] = f2tf(pa1.z); As[0][ak+7][am] = f2tf(pa1.w);
        uint4 u0 = make_uint4(f2tf(pb0.x), f2tf(pb0.y), f2tf(pb0.z), f2tf(pb0.w));
        uint4 u1 = make_uint4(f2tf(pb1.x), f2tf(pb1.y), f2tf(pb1.z), f2tf(pb1.w));
        *(uint4*)&Bs[0][bk][bn]     = u0;
        *(uint4*)&Bs[0][bk + 8][bn] = u1;
    }
    __syncthreads();

    for (int kt = 0; kt < 32; kt++) {
        const int cur = kt & 1;
        if (kt < 31) {
            const int k0 = (kt + 1) * 16;
            pa0 = *(const float4*)(Ap + k0);
            pa1 = *(const float4*)(Ap + k0 + 4);
            pb0 = *(const float4*)(Wp + (size_t)k0 * ND);
            pb1 = *(const float4*)(Wp + (size_t)(k0 + 8) * ND);
        }
#pragma unroll
        for (int ks = 0; ks < 16; ks += 8) {
            uint32_t af[2][4], bf[8][2];
#pragma unroll
            for (int mt = 0; mt < 2; mt++) {
                int m0 = wm * 32 + mt * 16 + gid;
                af[mt][0] = As[cur][ks + tig][m0];
                af[mt][1] = As[cur][ks + tig][m0 + 8];
                af[mt][2] = As[cur][ks + tig + 4][m0];
                af[mt][3] = As[cur][ks + tig + 4][m0 + 8];
            }
#pragma unroll
            for (int nt = 0; nt < 8; nt++) {
                int n0 = wn * 64 + nt * 8 + gid;
                bf[nt][0] = Bs[cur][ks + tig][n0];
                bf[nt][1] = Bs[cur][ks + tig + 4][n0];
            }
#pragma unroll
            for (int mt = 0; mt < 2; mt++)
#pragma unroll
                for (int nt = 0; nt < 8; nt++)
                    mma1688(acc[mt][nt], af[mt], bf[nt]);
        }
        if (kt < 31) {
            const int nxt = cur ^ 1;
            As[nxt][ak+0][am] = f2tf(pa0.x); As[nxt][ak+1][am] = f2tf(pa0.y);
            As[nxt][ak+2][am] = f2tf(pa0.z); As[nxt][ak+3][am] = f2tf(pa0.w);
            As[nxt][ak+4][am] = f2tf(pa1.x); As[nxt][ak+5][am] = f2tf(pa1.y);
            As[nxt][ak+6][am] = f2tf(pa1.z); As[nxt][ak+7][am] = f2tf(pa1.w);
            uint4 u0 = make_uint4(f2tf(pb0.x), f2tf(pb0.y), f2tf(pb0.z), f2tf(pb0.w));
            uint4 u1 = make_uint4(f2tf(pb1.x), f2tf(pb1.y), f2tf(pb1.z), f2tf(pb1.w));
            *(uint4*)&Bs[nxt][bk][bn]     = u0;
            *(uint4*)&Bs[nxt][bk + 8][bn] = u1;
        }
        __syncthreads();
    }

#pragma unroll
    for (int mt = 0; mt < 2; mt++) {
        int row = blockIdx.x * 128 + wm * 32 + mt * 16 + gid;
#pragma unroll
        for (int nt = 0; nt < 8; nt++) {
            int col = blockIdx.y * 128 + wn * 64 + nt * 8 + tig * 2;
            float v0 = acc[mt][nt][0], v1 = acc[mt][nt][1];
            float v2 = acc[mt][nt][2], v3 = acc[mt][nt][3];
            if (ACT == 1) { v0 = tanhf(v0); v1 = tanhf(v1); v2 = tanhf(v2); v3 = tanhf(v3); }
            *(float2*)(C + (size_t)row * ND + col)       = make_float2(v0, v1);
            *(float2*)(C + (size_t)(row + 8) * ND + col) = make_float2(v2, v3);
        }
    }
}

// ---------------- sequential LRU scan, v5 ----------------
// R1 skeleton (4-CTA cluster, warp owns 8 cols, lane owns k=l+32i), plus:
//  * W smem half packed bf16x2 (col pairs) -> 8 LDS.128/thread/step, lane-rotated slots
//  * f32x2 packed accumulate (64 FFMA2 vs 128 FFMA)
//  * 9-shfl log-tree reduction (vs 40); producer = lane 4c for col c
//  * h_prev register, precomputed mapa addresses
__global__ __launch_bounds__(512, 1) void scan_kernel(
    const float* __restrict__ nh, const float* __restrict__ ifg,
    const float* __restrict__ Whf, const float* __restrict__ bhf,
    float* __restrict__ hout)
{
    extern __shared__ float smem[];   // [0,64KB): bf16 W half; [64KB,+4KB): h double buf
    char*  wsm  = (char*)smem;
    float* hbuf = (float*)((char*)smem + 65536);

    const int rank  = blockIdx.x & 3;
    const int batch = blockIdx.x >> 2;
    const int tid = threadIdx.x;
    const int w = tid >> 5;
    const int l = tid & 31;
    const int jc = rank * 128 + w * 8;

    // register half: k = l + 32*i (i<8), cols jc..jc+7 as 4 b64 pairs per i
    unsigned long long Wreg[8][4];
#pragma unroll
    for (int i = 0; i < 8; i++) {
        const float* p = Whf + (size_t)(l + 32*i) * ND + jc;
        float4 a = *(const float4*)p;
        float4 b = *(const float4*)(p + 4);
        asm("mov.b64 %0,{%1,%2};" : "=l"(Wreg[i][0]) : "f"(a.x), "f"(a.y));
        asm("mov.b64 %0,{%1,%2};" : "=l"(Wreg[i][1]) : "f"(a.z), "f"(a.w));
        asm("mov.b64 %0,{%1,%2};" : "=l"(Wreg[i][2]) : "f"(b.x), "f"(b.y));
        asm("mov.b64 %0,{%1,%2};" : "=l"(Wreg[i][3]) : "f"(b.z), "f"(b.w));
    }
    // smem half: k = 256 + l + 32*i, bf16x2 col pairs, slot (i+l)&7 in 128B block
    const uint32_t wbase = (uint32_t)__cvta_generic_to_shared(wsm) + (uint32_t)tid * 128u;
#pragma unroll
    for (int i = 0; i < 8; i++) {
        const float* p = Whf + (size_t)(256 + l + 32*i) * ND + jc;
        float4 a = *(const float4*)p;
        float4 b = *(const float4*)(p + 4);
        uint32_t u0, u1, u2, u3;
        asm("cvt.rn.bf16x2.f32 %0, %1, %2;" : "=r"(u0) : "f"(a.y), "f"(a.x));
        asm("cvt.rn.bf16x2.f32 %0, %1, %2;" : "=r"(u1) : "f"(a.w), "f"(a.z));
        asm("cvt.rn.bf16x2.f32 %0, %1, %2;" : "=r"(u2) : "f"(b.y), "f"(b.x));
        asm("cvt.rn.bf16x2.f32 %0, %1, %2;" : "=r"(u3) : "f"(b.w), "f"(b.z));
        asm volatile("st.shared.v4.b32 [%0], {%1,%2,%3,%4};"
                     :: "r"(wbase + (uint32_t)(((i + l) & 7) * 16)),
                        "r"(u0), "r"(u1), "r"(u2), "r"(u3) : "memory");
    }
    hbuf[tid] = 0.f;
    hbuf[tid + 512] = 0.f;

    const uint32_t hbase = (uint32_t)__cvta_generic_to_shared(hbuf);

    // producer state: lanes with (l&3)==0 own column j = jc + (l>>2)
    const int isProd = ((l & 3) == 0);
    const int j = jc + (l >> 2);
    float bj = 0.f, h_prev = 0.f;
    const float *nhp = nullptr, *ifp = nullptr;
    float* hop = nullptr;
    uint32_t raddr[2][4];
    if (isProd) {
        bj = bhf[j];
        size_t off = (size_t)batch * NT * ND + j;
        nhp = nh + off; ifp = ifg + off; hop = hout + off;
#pragma unroll
        for (int buf = 0; buf < 2; buf++) {
            uint32_t la = hbase + (uint32_t)((buf * 512 + j) * 4);
#pragma unroll
            for (int rr = 0; rr < 4; rr++)
                asm("mapa.shared::cluster.u32 %0, %1, %2;"
                    : "=r"(raddr[buf][rr]) : "r"(la), "r"(rr));
        }
    }

    asm volatile("barrier.cluster.arrive.aligned;" ::: "memory");
    asm volatile("barrier.cluster.wait.aligned;"   ::: "memory");

    float nh_cur = 0.f, if_cur = 0.f;
    if (isProd) { nh_cur = nhp[0]; if_cur = ifp[0]; }

    const bool hi16 = (l & 16) != 0;
    const bool hi8  = (l & 8)  != 0;
    const bool hi4  = (l & 4)  != 0;

    for (int t = 0; t < NT; t++) {
        const float* hr = hbuf + (t & 1) * 512;
        float nh_nxt = 0.f, if_nxt = 0.f;
        if (isProd && t + 1 < NT) {
            nh_nxt = nhp[(size_t)(t+1) * ND];
            if_nxt = ifp[(size_t)(t+1) * ND];
        }
        unsigned long long a01 = 0ull, a23 = 0ull, a45 = 0ull, a67 = 0ull;
        // register half
#pragma unroll
        for (int i = 0; i < 8; i++) {
            float hk = hr[l + 32*i];
            unsigned long long hd;
            asm("mov.b64 %0,{%1,%1};" : "=l"(hd) : "f"(hk));
            asm volatile("fma.rn.f32x2 %0, %1, %2, %0;" : "+l"(a01) : "l"(hd), "l"(Wreg[i][0]));
            asm volatile("fma.rn.f32x2 %0, %1, %2, %0;" : "+l"(a23) : "l"(hd), "l"(Wreg[i][1]));
            asm volatile("fma.rn.f32x2 %0, %1, %2, %0;" : "+l"(a45) : "l"(hd), "l"(Wreg[i][2]));
            asm volatile("fma.rn.f32x2 %0, %1, %2, %0;" : "+l"(a67) : "l"(hd), "l"(Wreg[i][3]));
        }
        // smem half (bf16 W)
#pragma unroll
        for (int i = 0; i < 8; i++) {
            float hk = hr[256 + l + 32*i];
            unsigned long long hd;
            asm("mov.b64 %0,{%1,%1};" : "=l"(hd) : "f"(hk));
            uint32_t u0, u1, u2, u3;
            asm volatile("ld.shared.v4.b32 {%0,%1,%2,%3},[%4];"
                         : "=r"(u0), "=r"(u1), "=r"(u2), "=r"(u3)
                         : "r"(wbase + (uint32_t)(((i + l) & 7) * 16)));
            unsigned long long w01, w23, w45, w67;
            asm("{.reg .b32 lo,hi; shl.b32 lo,%1,16; and.b32 hi,%1,0xffff0000U; mov.b64 %0,{lo,hi};}"
                : "=l"(w01) : "r"(u0));
            asm("{.reg .b32 lo,hi; shl.b32 lo,%1,16; and.b32 hi,%1,0xffff0000U; mov.b64 %0,{lo,hi};}"
                : "=l"(w23) : "r"(u1));
            asm("{.reg .b32 lo,hi; shl.b32 lo,%1,16; and.b32 hi,%1,0xffff0000U; mov.b64 %0,{lo,hi};}"
                : "=l"(w45) : "r"(u2));
            asm("{.reg .b32 lo,hi; shl.b32 lo,%1,16; and.b32 hi,%1,0xffff0000U; mov.b64 %0,{lo,hi};}"
                : "=l"(w67) : "r"(u3));
            asm volatile("fma.rn.f32x2 %0, %1, %2, %0;" : "+l"(a01) : "l"(hd), "l"(w01));
            asm volatile("fma.rn.f32x2 %0, %1, %2, %0;" : "+l"(a23) : "l"(hd), "l"(w23));
            asm volatile("fma.rn.f32x2 %0, %1, %2, %0;" : "+l"(a45) : "l"(hd), "l"(w45));
            asm volatile("fma.rn.f32x2 %0, %1, %2, %0;" : "+l"(a67) : "l"(hd), "l"(w67));
        }
        // unpack
        float a0,a1,a2,a3,a4,a5,a6,a7;
        asm("mov.b64 {%0,%1},%2;" : "=f"(a0), "=f"(a1) : "l"(a01));
        asm("mov.b64 {%0,%1},%2;" : "=f"(a2), "=f"(a3) : "l"(a23));
        asm("mov.b64 {%0,%1},%2;" : "=f"(a4), "=f"(a5) : "l"(a45));
        asm("mov.b64 {%0,%1},%2;" : "=f"(a6), "=f"(a7) : "l"(a67));
        // log-tree reduction: 9 shfl
        // stage 1 (xor 16): low lanes keep cols 0-3, high keep 4-7
        float b0, b1, b2, b3;
        {
            float s0 = hi16 ? a0 : a4, k0 = hi16 ? a4 : a0;
            float s1 = hi16 ? a1 : a5, k1 = hi16 ? a5 : a1;
            float s2 = hi16 ? a2 : a6, k2 = hi16 ? a6 : a2;
            float s3 = hi16 ? a3 : a7, k3 = hi16 ? a7 : a3;
            b0 = k0 + __shfl_xor_sync(0xffffffffu, s0, 16);
            b1 = k1 + __shfl_xor_sync(0xffffffffu, s1, 16);
            b2 = k2 + __shfl_xor_sync(0xffffffffu, s2, 16);
            b3 = k3 + __shfl_xor_sync(0xffffffffu, s3, 16);
        }
        // stage 2 (xor 8)
        float d0, d1;
        {
            float s0 = hi8 ? b0 : b2, k0 = hi8 ? b2 : b0;
            float s1 = hi8 ? b1 : b3, k1 = hi8 ? b3 : b1;
            d0 = k0 + __shfl_xor_sync(0xffffffffu, s0, 8);
            d1 = k1 + __shfl_xor_sync(0xffffffffu, s1, 8);
        }
        // stage 3 (xor 4)
        float e;
        {
            float s = hi4 ? d0 : d1, k = hi4 ? d1 : d0;
            e = k + __shfl_xor_sync(0xffffffffu, s, 4);
        }
        // stages 4-5
        e += __shfl_xor_sync(0xffffffffu, e, 2);
        e += __shfl_xor_sync(0xffffffffu, e, 1);
        // producer lane 4c holds full sum of col jc+c
        if (isProd) {
            float z = e + bj + if_cur;
            float g = 1.f / (1.f + __expf(-z));
            float hn = fmaf(g, nh_cur - h_prev, h_prev);
            hop[(size_t)t * ND] = hn;
            h_prev = hn;
            const int nb = (t + 1) & 1;
            asm volatile("st.shared::cluster.f32 [%0], %1;" :: "r"(raddr[nb][0]), "f"(hn) : "memory");
            asm volatile("st.shared::cluster.f32 [%0], %1;" :: "r"(raddr[nb][1]), "f"(hn) : "memory");
            asm volatile("st.shared::cluster.f32 [%0], %1;" :: "r"(raddr[nb][2]), "f"(hn) : "memory");
            asm volatile("st.shared::cluster.f32 [%0], %1;" :: "r"(raddr[nb][3]), "f"(hn) : "memory");
        }
        nh_cur = nh_nxt; if_cur = if_nxt;
        asm volatile("barrier.cluster.arrive.aligned;" ::: "memory");
        asm volatile("barrier.cluster.wait.aligned;"   ::: "memory");
    }
}

// ---------------- gate cell combine + residual ----------------
__global__ __launch_bounds__(256) void combine_kernel(
    const float4* __restrict__ x,  const float4* __restrict__ xn,
    const float4* __restrict__ nh, const float4* __restrict__ ifb,
    const float4* __restrict__ hf, const float4* __restrict__ bhf,
    float4* __restrict__ out)
{
    size_t idx = (size_t)blockIdx.x * 256 + threadIdx.x;
    float4 xv = x[idx], xnv = xn[idx], nhv = nh[idx], iv = ifb[idx], hv = hf[idx];
    float4 bv = bhf[idx & 127];
    float4 o;
    { float z = hv.x + bv.x + iv.x; float g = 1.f/(1.f+__expf(-z)); o.x = xv.x + xnv.x + g*(nhv.x - xnv.x); }
    { float z = hv.y + bv.y + iv.y; float g = 1.f/(1.f+__expf(-z)); o.y = xv.y + xnv.y + g*(nhv.y - xnv.y); }
    { float z = hv.z + bv.z + iv.z; float g = 1.f/(1.f+__expf(-z)); o.z = xv.z + xnv.z + g*(nhv.z - xnv.z); }
    { float z = hv.w + bv.w + iv.w; float g = 1.f/(1.f+__expf(-z)); o.w = xv.w + xnv.w + g*(nhv.w - xnv.w); }
    out[idx] = o;
}

// ---------------- launch ----------------
static void launch_scan(const float* nh, const float* ifb,
                        const float* W, const float* b, float* ho)
{
    constexpr int SMEMB = 65536 + 4096;
    cudaFuncSetAttribute(scan_kernel, cudaFuncAttributeMaxDynamicSharedMemorySize, SMEMB);
    cudaLaunchConfig_t cfg = {};
    cfg.gridDim  = dim3(128, 1, 1);
    cfg.blockDim = dim3(512, 1, 1);
    cfg.dynamicSmemBytes = SMEMB;
    cfg.stream = 0;
    cudaLaunchAttribute attr;
    attr.id = cudaLaunchAttributeClusterDimension;
    attr.val.clusterDim.x = 4; attr.val.clusterDim.y = 1; attr.val.clusterDim.z = 1;
    cfg.attrs = &attr;
    cfg.numAttrs = 1;
    cudaLaunchKernelEx(&cfg, scan_kernel, nh, ifb, W, b, ho);
}

extern "C" void kernel_launch(void* const* d_in, const int* in_sizes, int n_in,
                              void* d_out, int out_size)
{
    const float* x     = (const float*)d_in[0];
    const float* gamma = (const float*)d_in[1];
    const float* gWn   = (const float*)d_in[2];
    const float* gWif  = (const float*)d_in[3];
    const float* gWhf  = (const float*)d_in[4];
    const float* gbhf  = (const float*)d_in[5];
    const float* l0Wn  = (const float*)d_in[6];
    const float* l0Wif = (const float*)d_in[7];
    const float* l0Whf = (const float*)d_in[8];
    const float* l0bhf = (const float*)d_in[9];
    const float* l1Wn  = (const float*)d_in[10];
    const float* l1Wif = (const float*)d_in[11];
    const float* l1Whf = (const float*)d_in[12];
    const float* l1bhf = (const float*)d_in[13];
    float* out = (float*)d_out;

    float *xn, *nh, *ifb, *hf, *h0, *h1;
    cudaGetSymbolAddress((void**)&xn,  g_xn);
    cudaGetSymbolAddress((void**)&nh,  g_nh);
    cudaGetSymbolAddress((void**)&ifb, g_ifb);
    cudaGetSymbolAddress((void**)&hf,  g_hf);
    cudaGetSymbolAddress((void**)&h0,  g_h0);
    cudaGetSymbolAddress((void**)&h1,  g_h1);

    dim3 gg(NROWS / 128, ND / 128);

    rmsnorm_kernel<<<NROWS / 8, 256>>>(x, gamma, xn);

    tgemm_kernel<1><<<gg, 256>>>(xn, l0Wn,  nh);
    tgemm_kernel<0><<<gg, 256>>>(xn, l0Wif, ifb);
    launch_scan(nh, ifb, l0Whf, l0bhf, h0);

    tgemm_kernel<1><<<gg, 256>>>(h0, l1Wn,  nh);
    tgemm_kernel<0><<<gg, 256>>>(h0, l1Wif, ifb);
    launch_scan(nh, ifb, l1Whf, l1bhf, h1);

    tgemm_kernel<1><<<gg, 256>>>(h1, gWn,  nh);
    tgemm_kernel<0><<<gg, 256>>>(h1, gWif, ifb);
    tgemm_kernel<0><<<gg, 256>>>(xn, gWhf, hf);

    combine_kernel<<<(NROWS * (ND/4)) / 256, 256>>>(
        (const float4*)x, (const float4*)xn, (const float4*)nh,
        (const float4*)ifb, (const float4*)hf, (const float4*)gbhf,
        (float4*)out);
}